// round 10
// baseline (speedup 1.0000x reference)
#include <cuda_runtime.h>

// MVKE fused kernel, v2. Bottleneck from R7 ncu: L1tex 75% (uncoalesced
// fc1_w reads in Phase C = ~32 wavefronts/instr; x staged through smem =
// 4 L1 passes), occupancy capped at 16 warps by 54KB smem.
// v2: warp-per-row coalesced gmem reads for Phase A/C (+shfl reduce),
// x never staged (Phase B re-read hits L2), smem 11KB, 6 CTAs/SM.
//
//   m1[b,s,v]  = x[b,s]·c1[v] + d1[v],   c1 = W1^T @ of2^T,  d1 = b1·of2
//   ws1[b,v]   = W1 @ y[b,v] + b1,       y[b,v] = sum_s sm1[s,v] x[b,s]
//   m2[b,t,v]  = tag[b,t]·c2[v] + d2[v]
//   out[b,t]   = sum_v sm2[t,v] * (ws1[b,v]·tag[b,t])

#define EE 100
#define E4 25          // float4 per 100-float row
#define VV 3
#define SS 100
#define TT 10
#define SCALE 0.1f     // 1/sqrt(DK), DK=100
#define PADV (-4294967295.0f)

__device__ float g_c1[VV * EE];
__device__ float g_d1[VV];
__device__ float g_c2[VV * EE];
__device__ float g_d2[VV];

__device__ __forceinline__ float dot4(float4 a, float4 b) {
    return a.x * b.x + a.y * b.y + a.z * b.z + a.w * b.w;
}

__global__ void mvke_precompute(const float* __restrict__ vk,
                                const float* __restrict__ fc1_w, const float* __restrict__ fc1_b,
                                const float* __restrict__ fc2_w, const float* __restrict__ fc2_b,
                                const float* __restrict__ fc3_w, const float* __restrict__ fc3_b,
                                const float* __restrict__ fc4_w, const float* __restrict__ fc4_b) {
    __shared__ float of2s[VV * EE];
    __shared__ float of3s[VV * EE];
    const int tid = threadIdx.x;
    const int w = tid >> 5, lane = tid & 31;
    const int nw = blockDim.x >> 5;

    // Stage 1: warp-per-(v,e). Lanes 0-24 read coalesced float4 rows of
    // fc2_w/fc3_w; vk rows preloaded per lane; shuffle-reduce 2 values.
    const float4* vk4 = (const float4*)vk;
    float4 zero4 = make_float4(0.f, 0.f, 0.f, 0.f);
    float4 vkv0 = zero4, vkv1 = zero4, vkv2 = zero4;
    if (lane < E4) {
        vkv0 = vk4[0 * E4 + lane];
        vkv1 = vk4[1 * E4 + lane];
        vkv2 = vk4[2 * E4 + lane];
    }
    const float4* w2_4 = (const float4*)fc2_w;
    const float4* w3_4 = (const float4*)fc3_w;
    for (int idx = w; idx < VV * EE; idx += nw) {
        int v = idx / EE, e = idx % EE;
        float4 xv = (v == 0) ? vkv0 : (v == 1) ? vkv1 : vkv2;
        float4 a = (lane < E4) ? w2_4[e * E4 + lane] : zero4;
        float4 c = (lane < E4) ? w3_4[e * E4 + lane] : zero4;
        float s2 = dot4(xv, a);
        float s3 = dot4(xv, c);
        #pragma unroll
        for (int o = 16; o; o >>= 1) {
            s2 += __shfl_xor_sync(0xffffffffu, s2, o);
            s3 += __shfl_xor_sync(0xffffffffu, s3, o);
        }
        if (lane == 0) {
            of2s[idx] = s2 + fc2_b[e];
            of3s[idx] = s3 + fc3_b[e];
        }
    }
    __syncthreads();

    // Stage 2: thread k owns output column k; fc1_w/fc4_w reads coalesced.
    if (tid < EE) {
        const int k = tid;
        float c1a[VV] = {0.f, 0.f, 0.f};
        float c2a[VV] = {0.f, 0.f, 0.f};
        #pragma unroll 4
        for (int e = 0; e < EE; e++) {
            float w1 = fc1_w[e * EE + k];
            float w4 = fc4_w[e * EE + k];
            #pragma unroll
            for (int v = 0; v < VV; v++) {
                c1a[v] += w1 * of2s[v * EE + e];
                c2a[v] += w4 * of3s[v * EE + e];
            }
        }
        #pragma unroll
        for (int v = 0; v < VV; v++) {
            g_c1[v * EE + k] = c1a[v];
            g_c2[v * EE + k] = c2a[v];
        }
    }
    if (tid < VV) {
        float d1 = 0.f, d2 = 0.f;
        for (int e = 0; e < EE; e++) {
            d1 += fc1_b[e] * of2s[tid * EE + e];
            d2 += fc4_b[e] * of3s[tid * EE + e];
        }
        g_d1[tid] = d1;
        g_d2[tid] = d2;
    }
}

// smem layout (floats) — x is NOT staged
#define OFF_TAGS  0                             // 1000
#define OFF_C1    (OFF_TAGS + TT * EE)          // +300
#define OFF_C2    (OFF_C1 + VV * EE)            // +300
#define OFF_M1    (OFF_C2 + VV * EE)            // +400  [s][4]
#define OFF_YS    (OFF_M1 + SS * 4)             // +300
#define OFF_WS1   (OFF_YS + VV * EE)            // +300
#define OFF_M2    (OFF_WS1 + VV * EE)           // +40
#define OFF_GS    (OFF_M2 + TT * 4)             // +40
#define OFF_D12   (OFF_GS + TT * 4)             // +8
#define OFF_B1    (OFF_D12 + 8)                 // +100
#define SMEM_FLOATS (OFF_B1 + EE)
#define SMEM_BYTES (SMEM_FLOATS * 4)

__global__ void __launch_bounds__(128, 6)
mvke_main(const float* __restrict__ x, const float* __restrict__ tag,
          const float* __restrict__ fc1_w, const float* __restrict__ fc1_b,
          float* __restrict__ out) {
    extern __shared__ float sm[];
    float* tags = sm + OFF_TAGS;
    float* c1s  = sm + OFF_C1;
    float* c2s  = sm + OFF_C2;
    float* m1s  = sm + OFF_M1;
    float* ys   = sm + OFF_YS;
    float* ws1s = sm + OFF_WS1;
    float* m2s  = sm + OFF_M2;
    float* gs   = sm + OFF_GS;
    float* d12  = sm + OFF_D12;
    float* b1s  = sm + OFF_B1;

    const int tid = threadIdx.x;
    const int w = tid >> 5, lane = tid & 31;
    const int b = blockIdx.x;
    const float4 zero4 = make_float4(0.f, 0.f, 0.f, 0.f);

    // ---- Phase 0: stage tag[b], constants (x stays in gmem) ----
    {
        const float4* t4 = (const float4*)(tag + (size_t)b * TT * EE);
        for (int i = tid; i < TT * E4; i += blockDim.x)
            ((float4*)tags)[i] = t4[i];
        for (int i = tid; i < VV * EE; i += blockDim.x) {
            c1s[i] = g_c1[i];
            c2s[i] = g_c2[i];
        }
        if (tid < EE) b1s[tid] = fc1_b[tid];
        if (tid < VV) { d12[tid] = g_d1[tid]; d12[4 + tid] = g_d2[tid]; }
    }
    __syncthreads();

    // ---- Phase A: warp-per-row. Lanes 0-24 read x row coalesced (4 lines),
    //      c1 columns preloaded into registers once; shuffle-reduce 4 vals ----
    {
        float4 c0v = zero4, c1v = zero4, c2v = zero4;
        if (lane < E4) {
            c0v = ((const float4*)(c1s + 0 * EE))[lane];
            c1v = ((const float4*)(c1s + 1 * EE))[lane];
            c2v = ((const float4*)(c1s + 2 * EE))[lane];
        }
        const float4* xb = (const float4*)(x + (size_t)b * SS * EE);
        #pragma unroll 5
        for (int s = w; s < SS; s += 4) {
            float4 xv = (lane < E4) ? __ldg(&xb[s * E4 + lane]) : zero4;
            float m0 = dot4(xv, c0v);
            float m1 = dot4(xv, c1v);
            float m2 = dot4(xv, c2v);
            float asum = fabsf(xv.x) + fabsf(xv.y) + fabsf(xv.z) + fabsf(xv.w);
            #pragma unroll
            for (int o = 16; o; o >>= 1) {
                m0   += __shfl_xor_sync(0xffffffffu, m0, o);
                m1   += __shfl_xor_sync(0xffffffffu, m1, o);
                m2   += __shfl_xor_sync(0xffffffffu, m2, o);
                asum += __shfl_xor_sync(0xffffffffu, asum, o);
            }
            if (lane == 0) {
                if (asum == 0.f) {
                    m1s[s * 4 + 0] = PADV; m1s[s * 4 + 1] = PADV; m1s[s * 4 + 2] = PADV;
                } else {
                    m1s[s * 4 + 0] = (m0 + d12[0]) * SCALE;
                    m1s[s * 4 + 1] = (m1 + d12[1]) * SCALE;
                    m1s[s * 4 + 2] = (m2 + d12[2]) * SCALE;
                }
            }
        }
    }
    __syncthreads();

    // ---- Phase A2: softmax over s per v (warp v owns column v), in place ----
    if (w < VV) {
        const int v = w;
        float vals[4];
        float mx = -3.4e38f;
        #pragma unroll
        for (int i = 0; i < 4; i++) {
            int s = lane + 32 * i;
            vals[i] = (s < SS) ? m1s[s * 4 + v] : -3.4e38f;
            mx = fmaxf(mx, vals[i]);
        }
        #pragma unroll
        for (int o = 16; o; o >>= 1) mx = fmaxf(mx, __shfl_xor_sync(0xffffffffu, mx, o));
        float ex[4];
        float ssum = 0.f;
        #pragma unroll
        for (int i = 0; i < 4; i++) {
            int s = lane + 32 * i;
            ex[i] = (s < SS) ? __expf(vals[i] - mx) : 0.f;
            ssum += ex[i];
        }
        #pragma unroll
        for (int o = 16; o; o >>= 1) ssum += __shfl_xor_sync(0xffffffffu, ssum, o);
        float inv = 1.f / ssum;
        #pragma unroll
        for (int i = 0; i < 4; i++) {
            int s = lane + 32 * i;
            if (s < SS) m1s[s * 4 + v] = ex[i] * inv;
        }
    }
    __syncthreads();

    // ---- Phase B: y[v,k] = sum_s sm1[s,v]*x[s,k]. Thread k: gmem reads
    //      coalesced across threads (L2-hot 40KB tile), m1s broadcast LDS ----
    if (tid < EE) {
        const int k = tid;
        const float* xc = x + (size_t)b * SS * EE + k;
        float a0 = 0.f, a1 = 0.f, a2 = 0.f;
        #pragma unroll 4
        for (int s = 0; s < SS; s++) {
            float xv = __ldg(xc + s * EE);
            float4 wv = ((const float4*)m1s)[s];
            a0 += wv.x * xv;
            a1 += wv.y * xv;
            a2 += wv.z * xv;
        }
        ys[0 * EE + k] = a0;
        ys[1 * EE + k] = a1;
        ys[2 * EE + k] = a2;
    }
    __syncthreads();

    // ---- Phase C: ws1[v,e] = W1[e,:]·y[v,:] + b1[e]. Warp-per-e with
    //      coalesced fc1_w row reads (4 lines, L1/L2-resident), y preloaded ----
    {
        float4 y0v = zero4, y1v = zero4, y2v = zero4;
        if (lane < E4) {
            y0v = ((const float4*)(ys + 0 * EE))[lane];
            y1v = ((const float4*)(ys + 1 * EE))[lane];
            y2v = ((const float4*)(ys + 2 * EE))[lane];
        }
        const float4* w1_4 = (const float4*)fc1_w;
        #pragma unroll 5
        for (int i = 0; i < E4; i++) {
            const int e = w * E4 + i;
            float4 wv = (lane < E4) ? __ldg(&w1_4[e * E4 + lane]) : zero4;
            float a0 = dot4(wv, y0v);
            float a1 = dot4(wv, y1v);
            float a2 = dot4(wv, y2v);
            #pragma unroll
            for (int o = 16; o; o >>= 1) {
                a0 += __shfl_xor_sync(0xffffffffu, a0, o);
                a1 += __shfl_xor_sync(0xffffffffu, a1, o);
                a2 += __shfl_xor_sync(0xffffffffu, a2, o);
            }
            if (lane == 0) {
                float bb = b1s[e];
                ws1s[0 * EE + e] = a0 + bb;
                ws1s[1 * EE + e] = a1 + bb;
                ws1s[2 * EE + e] = a2 + bb;
            }
        }
    }
    __syncthreads();

    // ---- Phase D: m2[t,v] = (tag[t]·c2[v]+d2[v])*scale ; g[t,v]=tag[t]·ws1[v] ----
    if (tid < TT * VV) {
        const int t = tid / VV, v = tid % VV;
        const float dv = d12[4 + v];
        float ma = 0.f, ga = 0.f;
        const float4* tr  = (const float4*)(tags + t * EE);
        const float4* cr  = (const float4*)(c2s + v * EE);
        const float4* wsr = (const float4*)(ws1s + v * EE);
        #pragma unroll 5
        for (int j = 0; j < E4; j++) {
            float4 tv = tr[j];
            ma += dot4(tv, cr[j]);
            ga += dot4(tv, wsr[j]);
        }
        m2s[t * 4 + v] = (ma + dv) * SCALE;
        gs[t * 4 + v] = ga;
    }
    __syncthreads();

    // ---- Phase E: softmax over t per v, then output ----
    if (tid < VV) {
        const int v = tid;
        float mx = -3.4e38f;
        #pragma unroll
        for (int t = 0; t < TT; t++) mx = fmaxf(mx, m2s[t * 4 + v]);
        float ssum = 0.f;
        float ex[TT];
        #pragma unroll
        for (int t = 0; t < TT; t++) { ex[t] = __expf(m2s[t * 4 + v] - mx); ssum += ex[t]; }
        float inv = 1.f / ssum;
        #pragma unroll
        for (int t = 0; t < TT; t++) m2s[t * 4 + v] = ex[t] * inv;
    }
    __syncthreads();
    if (tid < TT) {
        const int t = tid;
        out[(size_t)b * TT + t] = m2s[t * 4 + 0] * gs[t * 4 + 0]
                                + m2s[t * 4 + 1] * gs[t * 4 + 1]
                                + m2s[t * 4 + 2] * gs[t * 4 + 2];
    }
}

extern "C" void kernel_launch(void* const* d_in, const int* in_sizes, int n_in,
                              void* d_out, int out_size) {
    const float* x     = (const float*)d_in[0];
    const float* tag   = (const float*)d_in[1];
    const float* vk    = (const float*)d_in[2];
    const float* fc1_w = (const float*)d_in[3];
    const float* fc1_b = (const float*)d_in[4];
    const float* fc2_w = (const float*)d_in[5];
    const float* fc2_b = (const float*)d_in[6];
    const float* fc3_w = (const float*)d_in[7];
    const float* fc3_b = (const float*)d_in[8];
    const float* fc4_w = (const float*)d_in[9];
    const float* fc4_b = (const float*)d_in[10];
    float* out = (float*)d_out;

    int nb = in_sizes[0] / (SS * EE);

    mvke_precompute<<<1, 640>>>(vk, fc1_w, fc1_b, fc2_w, fc2_b, fc3_w, fc3_b, fc4_w, fc4_b);
    mvke_main<<<nb, 128, SMEM_BYTES>>>(x, tag, fc1_w, fc1_b, out);
}

// round 14
// speedup vs baseline: 1.2041x; 1.2041x over previous
#include <cuda_runtime.h>

// MVKE fused, v3. History: v1 (235us total): L1tex 75%, Phase C uncoalesced
// fc1_w (2500 wf/CTA) + x staged (occ 16w). v2 (315us, REGRESSED): shfl
// reductions moved the cost into MIO (3500 SHFL/CTA) — shuffles are not free.
// v3 = v1 structure (smem x, no shuffles) + pre-transposed W1 for Phase C
// (coalesced LDG.128) + vectorized 25-thread Phase B/C fused in warp 0.
//
//   m1[b,s,v]  = x[b,s]·c1[v] + d1[v],   c1 = W1^T @ of2^T,  d1 = b1·of2
//   ws1[b,v]   = W1 @ y[b,v] + b1,       y[b,v] = sum_s sm1[s,v] x[b,s]
//   m2[b,t,v]  = tag[b,t]·c2[v] + d2[v]
//   out[b,t]   = sum_v sm2[t,v] * (ws1[b,v]·tag[b,t])

#define EE 100
#define E4 25
#define VV 3
#define SS 100
#define TT 10
#define SCALE 0.1f
#define PADV (-4294967295.0f)
#define XPITCH 108   // 12 mod 32: conflict-free for row float4 AND column scalar

__device__ float g_c1[VV * EE];
__device__ float g_d1[VV];
__device__ float g_c2[VV * EE];
__device__ float g_d2[VV];
__device__ float g_w1t[EE * EE];   // g_w1t[k*100+e] = fc1_w[e*100+k]

__device__ __forceinline__ float dot4(float4 a, float4 b) {
    return a.x * b.x + a.y * b.y + a.z * b.z + a.w * b.w;
}
__device__ __forceinline__ void fma4(float4& acc, float s, float4 v) {
    acc.x += s * v.x; acc.y += s * v.y; acc.z += s * v.z; acc.w += s * v.w;
}

__global__ void mvke_precompute(const float* __restrict__ vk,
                                const float* __restrict__ fc1_w, const float* __restrict__ fc1_b,
                                const float* __restrict__ fc2_w, const float* __restrict__ fc2_b,
                                const float* __restrict__ fc3_w, const float* __restrict__ fc3_b,
                                const float* __restrict__ fc4_w, const float* __restrict__ fc4_b) {
    __shared__ float of2s[VV * EE];
    __shared__ float of3s[VV * EE];
    __shared__ float tile[EE * 101];   // padded transpose tile (40.4KB)
    const int tid = threadIdx.x;
    const int w = tid >> 5, lane = tid & 31;
    const int nw = blockDim.x >> 5;
    const float4 zero4 = make_float4(0.f, 0.f, 0.f, 0.f);

    // Load fc1_w coalesced into padded tile (for transpose after the sync).
    for (int i = tid; i < EE * EE; i += blockDim.x) {
        int e = i / EE, k = i % EE;
        tile[e * 101 + k] = fc1_w[i];
    }

    // Stage 1: of2[v,e], of3[v,e] — warp-per-output, coalesced weight rows.
    const float4* vk4 = (const float4*)vk;
    float4 vkv0 = zero4, vkv1 = zero4, vkv2 = zero4;
    if (lane < E4) {
        vkv0 = vk4[0 * E4 + lane];
        vkv1 = vk4[1 * E4 + lane];
        vkv2 = vk4[2 * E4 + lane];
    }
    const float4* w2_4 = (const float4*)fc2_w;
    const float4* w3_4 = (const float4*)fc3_w;
    for (int idx = w; idx < VV * EE; idx += nw) {
        int v = idx / EE, e = idx % EE;
        float4 xv = (v == 0) ? vkv0 : (v == 1) ? vkv1 : vkv2;
        float4 a = (lane < E4) ? w2_4[e * E4 + lane] : zero4;
        float4 c = (lane < E4) ? w3_4[e * E4 + lane] : zero4;
        float s2 = dot4(xv, a);
        float s3 = dot4(xv, c);
        #pragma unroll
        for (int o = 16; o; o >>= 1) {
            s2 += __shfl_xor_sync(0xffffffffu, s2, o);
            s3 += __shfl_xor_sync(0xffffffffu, s3, o);
        }
        if (lane == 0) {
            of2s[idx] = s2 + fc2_b[e];
            of3s[idx] = s3 + fc3_b[e];
        }
    }
    __syncthreads();

    // Transpose out of tile: write g_w1t coalesced, read pitch-101 (conflict-free).
    for (int i = tid; i < EE * EE; i += blockDim.x) {
        int k = i / EE, e = i % EE;
        g_w1t[i] = tile[e * 101 + k];
    }

    // Stage 2: c1[v,k], c2[v,k] — thread-per-k, coalesced weight reads.
    if (tid < EE) {
        const int k = tid;
        float c1a[VV] = {0.f, 0.f, 0.f};
        float c2a[VV] = {0.f, 0.f, 0.f};
        #pragma unroll 4
        for (int e = 0; e < EE; e++) {
            float w1 = fc1_w[e * EE + k];
            float w4 = fc4_w[e * EE + k];
            #pragma unroll
            for (int v = 0; v < VV; v++) {
                c1a[v] += w1 * of2s[v * EE + e];
                c2a[v] += w4 * of3s[v * EE + e];
            }
        }
        #pragma unroll
        for (int v = 0; v < VV; v++) {
            g_c1[v * EE + k] = c1a[v];
            g_c2[v * EE + k] = c2a[v];
        }
    }
    if (tid < VV) {
        float d1 = 0.f, d2 = 0.f;
        for (int e = 0; e < EE; e++) {
            d1 += fc1_b[e] * of2s[tid * EE + e];
            d2 += fc4_b[e] * of3s[tid * EE + e];
        }
        g_d1[tid] = d1;
        g_d2[tid] = d2;
    }
}

// smem layout (floats)
#define OFF_XS    0                             // 10800
#define OFF_TAGS  (OFF_XS + SS * XPITCH)        // +1000
#define OFF_C1    (OFF_TAGS + TT * EE)          // +300
#define OFF_C2    (OFF_C1 + VV * EE)            // +300
#define OFF_M1    (OFF_C2 + VV * EE)            // +400  [s][4]
#define OFF_YS4   (OFF_M1 + SS * 4)             // +400  [k][4] packed {y0,y1,y2,-}
#define OFF_WS1   (OFF_YS4 + SS * 4)            // +300
#define OFF_M2    (OFF_WS1 + VV * EE)           // +40
#define OFF_GS    (OFF_M2 + TT * 4)             // +40
#define OFF_D12   (OFF_GS + TT * 4)             // +8
#define SMEM_FLOATS (OFF_D12 + 8)
#define SMEM_BYTES (SMEM_FLOATS * 4)

__global__ void __launch_bounds__(128, 4)
mvke_main(const float* __restrict__ x, const float* __restrict__ tag,
          const float* __restrict__ fc1_w, const float* __restrict__ fc1_b,
          float* __restrict__ out) {
    extern __shared__ float sm[];
    float* xs   = sm + OFF_XS;
    float* tags = sm + OFF_TAGS;
    float* c1s  = sm + OFF_C1;
    float* c2s  = sm + OFF_C2;
    float* m1s  = sm + OFF_M1;
    float* ys4  = sm + OFF_YS4;
    float* ws1s = sm + OFF_WS1;
    float* m2s  = sm + OFF_M2;
    float* gs   = sm + OFF_GS;
    float* d12  = sm + OFF_D12;

    const int tid = threadIdx.x;
    const int w = tid >> 5, lane = tid & 31;
    const int b = blockIdx.x;

    // ---- Phase 0: stage x (pitch 108), tag, constants ----
    {
        const float4* x4 = (const float4*)(x + (size_t)b * SS * EE);
        for (int i = tid; i < SS * E4; i += blockDim.x) {
            int row = i / E4, col = i % E4;
            ((float4*)(xs + row * XPITCH))[col] = x4[i];
        }
        const float4* t4 = (const float4*)(tag + (size_t)b * TT * EE);
        for (int i = tid; i < TT * E4; i += blockDim.x)
            ((float4*)tags)[i] = t4[i];
        for (int i = tid; i < VV * EE; i += blockDim.x) {
            c1s[i] = g_c1[i];
            c2s[i] = g_c2[i];
        }
        if (tid < VV) { d12[tid] = g_d1[tid]; d12[4 + tid] = g_d2[tid]; }
    }
    __syncthreads();

    // ---- Phase A: thread-per-s, x row LDS.128 (conflict-free), c broadcast ----
    if (tid < SS) {
        const int s = tid;
        const float b0 = d12[0], b1v = d12[1], b2v = d12[2];
        float m0 = 0.f, m1 = 0.f, m2 = 0.f, asum = 0.f;
        const float4* xr  = (const float4*)(xs + s * XPITCH);
        const float4* c0r = (const float4*)(c1s + 0 * EE);
        const float4* c1r = (const float4*)(c1s + 1 * EE);
        const float4* c2r = (const float4*)(c1s + 2 * EE);
        #pragma unroll 5
        for (int j = 0; j < E4; j++) {
            float4 xv = xr[j];
            asum += fabsf(xv.x) + fabsf(xv.y) + fabsf(xv.z) + fabsf(xv.w);
            float4 a = c0r[j], bb = c1r[j], c = c2r[j];
            m0 += dot4(xv, a);
            m1 += dot4(xv, bb);
            m2 += dot4(xv, c);
        }
        if (asum == 0.f) {
            m1s[s * 4 + 0] = PADV; m1s[s * 4 + 1] = PADV; m1s[s * 4 + 2] = PADV;
        } else {
            m1s[s * 4 + 0] = (m0 + b0) * SCALE;
            m1s[s * 4 + 1] = (m1 + b1v) * SCALE;
            m1s[s * 4 + 2] = (m2 + b2v) * SCALE;
        }
    }
    __syncthreads();

    // ---- Phase A2: softmax over s per v (warp v owns column v) ----
    if (w < VV) {
        const int v = w;
        float vals[4];
        float mx = -3.4e38f;
        #pragma unroll
        for (int i = 0; i < 4; i++) {
            int s = lane + 32 * i;
            vals[i] = (s < SS) ? m1s[s * 4 + v] : -3.4e38f;
            mx = fmaxf(mx, vals[i]);
        }
        #pragma unroll
        for (int o = 16; o; o >>= 1) mx = fmaxf(mx, __shfl_xor_sync(0xffffffffu, mx, o));
        float ex[4];
        float ssum = 0.f;
        #pragma unroll
        for (int i = 0; i < 4; i++) {
            int s = lane + 32 * i;
            ex[i] = (s < SS) ? __expf(vals[i] - mx) : 0.f;
            ssum += ex[i];
        }
        #pragma unroll
        for (int o = 16; o; o >>= 1) ssum += __shfl_xor_sync(0xffffffffu, ssum, o);
        float inv = 1.f / ssum;
        #pragma unroll
        for (int i = 0; i < 4; i++) {
            int s = lane + 32 * i;
            if (s < SS) m1s[s * 4 + v] = ex[i] * inv;
        }
    }
    __syncthreads();

    // ---- Phase B + C fused in warp 0, 25 threads, 4 columns each ----
    if (tid < E4) {
        const int t = tid;
        // B: y[v, 4t..4t+3] = sum_s sm1[s,v] * x[s, 4t..4t+3]
        float4 av0 = make_float4(0.f, 0.f, 0.f, 0.f);
        float4 av1 = av0, av2 = av0;
        #pragma unroll 4
        for (int s = 0; s < SS; s++) {
            float4 xv = ((const float4*)(xs + s * XPITCH))[t];
            float4 wv = ((const float4*)m1s)[s];
            fma4(av0, wv.x, xv);
            fma4(av1, wv.y, xv);
            fma4(av2, wv.z, xv);
        }
        ((float4*)ys4)[4 * t + 0] = make_float4(av0.x, av1.x, av2.x, 0.f);
        ((float4*)ys4)[4 * t + 1] = make_float4(av0.y, av1.y, av2.y, 0.f);
        ((float4*)ys4)[4 * t + 2] = make_float4(av0.z, av1.z, av2.z, 0.f);
        ((float4*)ys4)[4 * t + 3] = make_float4(av0.w, av1.w, av2.w, 0.f);
        __syncwarp(0x01ffffffu);

        // C: ws1[v, 4t..4t+3] = b1 + sum_k W1t[k, 4t..4t+3] * y[v,k]
        float4 bv = __ldg(((const float4*)fc1_b) + t);
        float4 acc0 = bv, acc1 = bv, acc2 = bv;
        const float4* w1t4 = (const float4*)g_w1t;
        #pragma unroll 4
        for (int k = 0; k < SS; k++) {
            float4 wv = __ldg(&w1t4[k * E4 + t]);   // coalesced, L1-resident
            float4 yv = ((const float4*)ys4)[k];     // broadcast
            fma4(acc0, yv.x, wv);
            fma4(acc1, yv.y, wv);
            fma4(acc2, yv.z, wv);
        }
        ws1s[0 * EE + 4 * t + 0] = acc0.x; ws1s[0 * EE + 4 * t + 1] = acc0.y;
        ws1s[0 * EE + 4 * t + 2] = acc0.z; ws1s[0 * EE + 4 * t + 3] = acc0.w;
        ws1s[1 * EE + 4 * t + 0] = acc1.x; ws1s[1 * EE + 4 * t + 1] = acc1.y;
        ws1s[1 * EE + 4 * t + 2] = acc1.z; ws1s[1 * EE + 4 * t + 3] = acc1.w;
        ws1s[2 * EE + 4 * t + 0] = acc2.x; ws1s[2 * EE + 4 * t + 1] = acc2.y;
        ws1s[2 * EE + 4 * t + 2] = acc2.z; ws1s[2 * EE + 4 * t + 3] = acc2.w;
    }
    __syncthreads();

    // ---- Phase D: m2[t,v], g[t,v] ----
    if (tid < TT * VV) {
        const int t = tid / VV, v = tid % VV;
        const float dv = d12[4 + v];
        float ma = 0.f, ga = 0.f;
        const float4* tr  = (const float4*)(tags + t * EE);
        const float4* cr  = (const float4*)(c2s + v * EE);
        const float4* wsr = (const float4*)(ws1s + v * EE);
        #pragma unroll 5
        for (int j = 0; j < E4; j++) {
            float4 tv = tr[j];
            ma += dot4(tv, cr[j]);
            ga += dot4(tv, wsr[j]);
        }
        m2s[t * 4 + v] = (ma + dv) * SCALE;
        gs[t * 4 + v] = ga;
    }
    __syncthreads();

    // ---- Phase E: softmax over t per v, then output ----
    if (tid < VV) {
        const int v = tid;
        float mx = -3.4e38f;
        #pragma unroll
        for (int t = 0; t < TT; t++) mx = fmaxf(mx, m2s[t * 4 + v]);
        float ssum = 0.f;
        float ex[TT];
        #pragma unroll
        for (int t = 0; t < TT; t++) { ex[t] = __expf(m2s[t * 4 + v] - mx); ssum += ex[t]; }
        float inv = 1.f / ssum;
        #pragma unroll
        for (int t = 0; t < TT; t++) m2s[t * 4 + v] = ex[t] * inv;
    }
    __syncthreads();
    if (tid < TT) {
        const int t = tid;
        out[(size_t)b * TT + t] = m2s[t * 4 + 0] * gs[t * 4 + 0]
                                + m2s[t * 4 + 1] * gs[t * 4 + 1]
                                + m2s[t * 4 + 2] * gs[t * 4 + 2];
    }
}

extern "C" void kernel_launch(void* const* d_in, const int* in_sizes, int n_in,
                              void* d_out, int out_size) {
    const float* x     = (const float*)d_in[0];
    const float* tag   = (const float*)d_in[1];
    const float* vk    = (const float*)d_in[2];
    const float* fc1_w = (const float*)d_in[3];
    const float* fc1_b = (const float*)d_in[4];
    const float* fc2_w = (const float*)d_in[5];
    const float* fc2_b = (const float*)d_in[6];
    const float* fc3_w = (const float*)d_in[7];
    const float* fc3_b = (const float*)d_in[8];
    const float* fc4_w = (const float*)d_in[9];
    const float* fc4_b = (const float*)d_in[10];
    float* out = (float*)d_out;

    int nb = in_sizes[0] / (SS * EE);

    cudaFuncSetAttribute(mvke_main, cudaFuncAttributeMaxDynamicSharedMemorySize, SMEM_BYTES);

    mvke_precompute<<<1, 640>>>(vk, fc1_w, fc1_b, fc2_w, fc2_b, fc3_w, fc3_b, fc4_w, fc4_b);
    mvke_main<<<nb, 128, SMEM_BYTES>>>(x, tag, fc1_w, fc1_b, out);
}